// round 2
// baseline (speedup 1.0000x reference)
#include <cuda_runtime.h>
#include <cuda_bf16.h>
#include <math.h>

// ---------------------------------------------------------------------------
// YOLO post-process: decode 3 heads -> conf threshold -> per-image top-100
// (sorted desc, lower-index-first ties) -> greedy class-aware NMS.
//
// Inputs: out13 [B,255,13,13], out26 [B,255,26,26], out52 [B,255,52,52],
//         anchors [3,3,2], thresh scalar (all f32)
// Output: f32, sel [B,100,6] flattened, then keep [B,100] as 0/1 floats.
//
// Two launches:
//   K1 (grid B*8): compact valid candidates per (batch,chunk) region.
//   K2 (grid B):   histogram -> exact top-100 -> decode -> NMS -> write out.
// ---------------------------------------------------------------------------

#define BMAX   32
#define KNMS   100
#define NBOX   10647           // (169+676+2704)*3
#define N1     507             // 13*13*3
#define N12    2535            // N1 + 26*26*3
#define NCHUNK 8
#define CHUNK  1331            // ceil(NBOX/NCHUNK)
#define CANDCAP 4096

__device__ unsigned long long g_cand[BMAX * NCHUNK * CHUNK];
__device__ int                g_ccnt[BMAX * NCHUNK];

// map global box index n -> plane base for batch b, and geometry
__device__ __forceinline__ void map_box(
    int n, int b,
    const float* o13, const float* o26, const float* o52,
    const float** base, int* SS, int* S, int* scale, int* a, int* cell)
{
    int nl;
    if (n < N1)       { *base = o13 + (size_t)b * 255 * 169;  *SS = 169;  *S = 13; *scale = 0; nl = n; }
    else if (n < N12) { *base = o26 + (size_t)b * 255 * 676;  *SS = 676;  *S = 26; *scale = 1; nl = n - N1; }
    else              { *base = o52 + (size_t)b * 255 * 2704; *SS = 2704; *S = 52; *scale = 2; nl = n - N12; }
    *a = nl % 3;
    *cell = nl / 3;
}

__device__ __forceinline__ float box_score(
    int n, int b, const float* o13, const float* o26, const float* o52, float th)
{
    const float* base; int SS, S, scale, a, cell;
    map_box(n, b, o13, o26, o52, &base, &SS, &S, &scale, &a, &cell);
    float lg = base[(size_t)(a * 85) * SS + cell];
    float conf = 1.f / (1.f + expf(-lg));
    return (conf > th) ? conf : 0.f;
}

// ---------------------------------------------------------------------------
// K1: per-(batch,chunk) candidate compaction. grid = B*8, 256 threads.
// ---------------------------------------------------------------------------
__global__ __launch_bounds__(256)
void cand_kernel(const float* __restrict__ o13,
                 const float* __restrict__ o26,
                 const float* __restrict__ o52,
                 const float* __restrict__ thresh_p)
{
    __shared__ unsigned int cnt_s;
    const int b     = blockIdx.x >> 3;
    const int chunk = blockIdx.x & 7;
    const int tid   = threadIdx.x;
    const float th  = *thresh_p;

    // logit-space early-out bound (margin >> fp32 rounding of sigmoid)
    float L;
    if (th > 0.f && th < 1.f)      L = __logf(th / (1.f - th)) - 1e-3f;
    else if (th >= 1.f)            L =  INFINITY;
    else                           L = -INFINITY;

    if (tid == 0) cnt_s = 0u;
    __syncthreads();

    const int n0 = chunk * CHUNK;
    const int n1 = min(n0 + CHUNK, NBOX);
    unsigned long long* reg = g_cand + (size_t)(b * NCHUNK + chunk) * CHUNK;

    for (int n = n0 + tid; n < n1; n += 256) {
        const float* base; int SS, S, scale, a, cell;
        map_box(n, b, o13, o26, o52, &base, &SS, &S, &scale, &a, &cell);
        float lg = __ldg(base + (size_t)(a * 85) * SS + cell);
        if (lg > L) {
            float conf = 1.f / (1.f + expf(-lg));    // exact reference compare
            if (conf > th) {
                unsigned int pos = atomicAdd(&cnt_s, 1u);
                reg[pos] = ((unsigned long long)__float_as_uint(conf) << 32)
                         | (unsigned long long)(0xFFFFFFFFu - (unsigned)n);
            }
        }
    }
    __syncthreads();
    if (tid == 0) g_ccnt[b * NCHUNK + chunk] = (int)cnt_s;
}

// ---------------------------------------------------------------------------
// K2: per-batch fused top-100 select + decode + NMS. grid = B, 1024 threads.
// ---------------------------------------------------------------------------
__global__ __launch_bounds__(1024)
void fused_kernel(const float* __restrict__ o13,
                  const float* __restrict__ o26,
                  const float* __restrict__ o52,
                  const float* __restrict__ anchors,
                  const float* __restrict__ thresh_p,
                  float* __restrict__ out, int B)
{
    __shared__ unsigned int hist[132];
    __shared__ unsigned long long cand[CANDCAP];
    __shared__ unsigned int nc_s;
    __shared__ int bt_s;
    __shared__ int  s_idx[KNMS];
    __shared__ float s_score[KNMS];
    __shared__ float bx1[KNMS], by1[KNMS], bx2[KNMS], by2[KNMS], bcl[KNMS], bar[KNMS];
    __shared__ unsigned int sup[KNMS * 4];
    __shared__ unsigned int keepm[4];

    const int b   = blockIdx.x;
    const int tid = threadIdx.x;

    if (tid < 132) hist[tid] = 0u;
    if (tid == 0) nc_s = 0u;
    if (tid < 4)  keepm[tid] = 0u;
    if (tid < KNMS * 4) sup[tid] = 0u;
    __syncthreads();

    // ---- pass 1: histogram over candidate scores -------------------------
    int cnts[NCHUNK];
    int validtot = 0;
#pragma unroll
    for (int r = 0; r < NCHUNK; r++) { cnts[r] = g_ccnt[b * NCHUNK + r]; validtot += cnts[r]; }

#pragma unroll
    for (int r = 0; r < NCHUNK; r++) {
        const unsigned long long* reg = g_cand + (size_t)(b * NCHUNK + r) * CHUNK;
        for (int i = tid; i < cnts[r]; i += 1024) {
            int bb = (int)(reg[i] >> 48) - 0x3F00 + 1;
            bb = bb < 1 ? 1 : (bb > 128 ? 128 : bb);
            atomicAdd(&hist[bb], 1u);
        }
    }
    __syncthreads();

    if (tid == 0) {
        unsigned int cum = 0; int bt = 1;
        for (int bb = 128; bb >= 1; bb--) {
            cum += hist[bb];
            if (cum >= KNMS) { bt = bb; break; }
        }
        bt_s = bt;
    }
    __syncthreads();
    const int bt = bt_s;

    // ---- pass 2: filter survivors into shared ----------------------------
#pragma unroll
    for (int r = 0; r < NCHUNK; r++) {
        const unsigned long long* reg = g_cand + (size_t)(b * NCHUNK + r) * CHUNK;
        for (int i = tid; i < cnts[r]; i += 1024) {
            unsigned long long key = reg[i];
            int bb = (int)(key >> 48) - 0x3F00 + 1;
            bb = bb < 1 ? 1 : (bb > 128 ? 128 : bb);
            if (bb >= bt) {
                unsigned int pos = atomicAdd(&nc_s, 1u);
                if (pos < CANDCAP) cand[pos] = key;
            }
        }
    }
    __syncthreads();
    unsigned int nc = nc_s; if (nc > CANDCAP) nc = CANDCAP;

    // ---- exact rank selection (keys unique via embedded index) -----------
    for (unsigned int c = tid; c < nc; c += 1024) {
        unsigned long long kc = cand[c];
        int rank = 0;
        for (unsigned int j = 0; j < nc; j++)
            rank += (cand[j] > kc) ? 1 : 0;
        if (rank < KNMS) {
            s_idx[rank]   = (int)(0xFFFFFFFFu - (unsigned)(kc & 0xFFFFFFFFull));
            s_score[rank] = __uint_as_float((unsigned)(kc >> 32));
        }
    }
    __syncthreads();

    // ---- fallback: fewer than K valid boxes ------------------------------
    if (validtot < KNMS && tid == 0) {
        const float th = *thresh_p;
        int filled = validtot;
        for (int n = 0; n < NBOX && filled < KNMS; n++) {
            if (box_score(n, b, o13, o26, o52, th) == 0.f) {
                s_idx[filled] = n; s_score[filled] = 0.f; filled++;
            }
        }
    }
    __syncthreads();

    // ---- decode: warp per box, 4 boxes per warp --------------------------
    const int w    = tid >> 5;
    const int lane = tid & 31;
#pragma unroll
    for (int rep = 0; rep < 4; rep++) {
        int k = w + rep * 32;
        if (k >= KNMS) break;
        int n = s_idx[k];

        const float* base; int SS, S, scale, a, cell;
        map_box(n, b, o13, o26, o52, &base, &SS, &S, &scale, &a, &cell);
        const float* p = base + (size_t)(a * 85) * SS + cell;
        float stridef = (scale == 0) ? 32.f : (scale == 1 ? 16.f : 8.f);
        int y = cell / S, x = cell % S;

        float f = (lane < 5) ? __ldg(p + (size_t)lane * SS) : 0.f;
        float f0 = __shfl_sync(0xFFFFFFFFu, f, 0);
        float f1 = __shfl_sync(0xFFFFFFFFu, f, 1);
        float f2 = __shfl_sync(0xFFFFFFFFu, f, 2);
        float f3 = __shfl_sync(0xFFFFFFFFu, f, 3);
        float f4 = __shfl_sync(0xFFFFFFFFu, f, 4);

        // 80-class argmax, first-max-wins
        unsigned long long best = 0ull;
#pragma unroll
        for (int c = lane; c < 80; c += 32) {
            float v = __ldg(p + (size_t)(5 + c) * SS);
            unsigned u = __float_as_uint(v);
            u = (u & 0x80000000u) ? ~u : (u | 0x80000000u);
            unsigned long long key = ((unsigned long long)u << 32)
                                   | (unsigned long long)(127u - (unsigned)c);
            if (key > best) best = key;
        }
#pragma unroll
        for (int off = 16; off; off >>= 1) {
            unsigned long long o2 = __shfl_xor_sync(0xFFFFFFFFu, best, off);
            if (o2 > best) best = o2;
        }
        int cls = 127 - (int)(best & 0xFFFFFFFFull);

        if (lane == 0) {
            float conf = 1.f / (1.f + expf(-f0));
            float sx   = 1.f / (1.f + expf(-f1));
            float sy   = 1.f / (1.f + expf(-f2));
            float ox = ((float)x + sx) * stridef;
            float oy = ((float)y + sy) * stridef;
            float wd = expf(f3) * __ldg(anchors + scale * 6 + a * 2 + 0);
            float ht = expf(f4) * __ldg(anchors + scale * 6 + a * 2 + 1);
            float X1 = ox - wd * 0.5f, Y1 = oy - ht * 0.5f;
            float X2 = ox + wd * 0.5f, Y2 = oy + ht * 0.5f;
            float* o = out + (size_t)(b * KNMS + k) * 6;
            o[0] = X1; o[1] = Y1; o[2] = X2; o[3] = Y2;
            o[4] = (float)cls; o[5] = conf;
            bx1[k] = X1; by1[k] = Y1; bx2[k] = X2; by2[k] = Y2;
            bcl[k] = (float)cls;
            bar[k] = fmaxf(X2 - X1, 0.f) * fmaxf(Y2 - Y1, 0.f);
        }
    }
    // keep-init bits
    if (tid < KNMS && s_score[tid] > 0.f)
        atomicOr(&keepm[tid >> 5], 1u << (tid & 31));
    __syncthreads();

    // ---- NMS: parallel suppression bitmask -------------------------------
    for (int pr = tid; pr < KNMS * KNMS; pr += 1024) {
        int i = pr / KNMS, j = pr % KNMS;
        if (j > i && bcl[i] == bcl[j]) {
            float xx1 = fmaxf(bx1[i], bx1[j]);
            float yy1 = fmaxf(by1[i], by1[j]);
            float xx2 = fminf(bx2[i], bx2[j]);
            float yy2 = fminf(by2[i], by2[j]);
            float inter = fmaxf(xx2 - xx1, 0.f) * fmaxf(yy2 - yy1, 0.f);
            float uni   = bar[i] + bar[j] - inter;
            float iou   = inter / fmaxf(uni, 1e-9f);
            if (iou > 0.3f)
                atomicOr(&sup[i * 4 + (j >> 5)], 1u << (j & 31));
        }
    }
    __syncthreads();

    // ---- serial greedy walk (thread 0, ~100 bit-ops) ---------------------
    if (tid == 0) {
        unsigned int k0 = keepm[0], k1 = keepm[1], k2 = keepm[2], k3 = keepm[3];
        for (int i = 0; i < KNMS; i++) {
            unsigned int word = (i < 32) ? k0 : (i < 64) ? k1 : (i < 96) ? k2 : k3;
            if ((word >> (i & 31)) & 1u) {
                k0 &= ~sup[i * 4 + 0];
                k1 &= ~sup[i * 4 + 1];
                k2 &= ~sup[i * 4 + 2];
                k3 &= ~sup[i * 4 + 3];
            }
        }
        keepm[0] = k0; keepm[1] = k1; keepm[2] = k2; keepm[3] = k3;
    }
    __syncthreads();

    if (tid < KNMS)
        out[(size_t)B * KNMS * 6 + b * KNMS + tid] =
            ((keepm[tid >> 5] >> (tid & 31)) & 1u) ? 1.f : 0.f;
}

// ---------------------------------------------------------------------------
extern "C" void kernel_launch(void* const* d_in, const int* in_sizes, int n_in,
                              void* d_out, int out_size)
{
    const float* o13     = (const float*)d_in[0];
    const float* o26     = (const float*)d_in[1];
    const float* o52     = (const float*)d_in[2];
    const float* anchors = (const float*)d_in[3];
    const float* thresh  = (const float*)d_in[4];
    float* out = (float*)d_out;

    int B = in_sizes[0] / (255 * 169);
    if (B > BMAX) B = BMAX;

    cand_kernel<<<B * NCHUNK, 256>>>(o13, o26, o52, thresh);
    fused_kernel<<<B, 1024>>>(o13, o26, o52, anchors, thresh, out, B);
}